// round 5
// baseline (speedup 1.0000x reference)
#include <cuda_runtime.h>

#define A_NUM 5
#define EPSV 1e-10f

// ---------------- batch-independent precomputed parameters ----------------
__device__ float g_Qt[64];
__device__ float g_G[64];   // Qt @ Qr
__device__ float g_Qy[64];
__device__ float g_wr[A_NUM];
__device__ float g_ws[A_NUM];
__device__ float g_t;

// 8x8 Cayley transform: Q = inv(I - Bm) @ (I + Bm), Bm = L - L^T,
// L[i+1][c] = b[i+c] for c in [0, i]  (reference's mapping).
__device__ void cayley8(const float* __restrict__ b, float* __restrict__ Q) {
    float Bm[8][8];
    for (int i = 0; i < 8; i++)
        for (int j = 0; j < 8; j++) Bm[i][j] = 0.0f;
    for (int i = 0; i < 7; i++)
        for (int c = 0; c <= i; c++) Bm[i + 1][c] = b[i + c];

    float A[8][16];
    for (int i = 0; i < 8; i++) {
        for (int j = 0; j < 8; j++) {
            float v = Bm[i][j] - Bm[j][i];
            float d = (i == j) ? 1.0f : 0.0f;
            A[i][j]     = d - v;   // I - Bm
            A[i][j + 8] = d + v;   // I + Bm
        }
    }
    for (int k = 0; k < 8; k++) {
        int p = k;
        float best = fabsf(A[k][k]);
        for (int r = k + 1; r < 8; r++) {
            float v = fabsf(A[r][k]);
            if (v > best) { best = v; p = r; }
        }
        if (p != k) {
            for (int j = 0; j < 16; j++) {
                float tmp = A[k][j]; A[k][j] = A[p][j]; A[p][j] = tmp;
            }
        }
        float inv = 1.0f / A[k][k];
        for (int j = 0; j < 16; j++) A[k][j] *= inv;
        for (int r = 0; r < 8; r++) {
            if (r == k) continue;
            float f = A[r][k];
            for (int j = 0; j < 16; j++) A[r][j] -= f * A[k][j];
        }
    }
    for (int i = 0; i < 8; i++)
        for (int j = 0; j < 8; j++) Q[i * 8 + j] = A[i][j + 8];
}

__global__ void spdsru_prologue(const float* __restrict__ kr,
                                const float* __restrict__ kt,
                                const float* __restrict__ kphi,
                                const float* __restrict__ ks,
                                const float* __restrict__ br,
                                const float* __restrict__ bt,
                                const float* __restrict__ by) {
    __shared__ float sQr[64];
    __shared__ float sQt[64];
    int tid = threadIdx.x;
    if (tid < 3) {
        const float* bias = (tid == 0) ? br : ((tid == 1) ? bt : by);
        float Q[64];
        cayley8(bias, Q);
        if (tid == 0) {
            for (int i = 0; i < 64; i++) sQr[i] = Q[i];
        } else if (tid == 1) {
            for (int i = 0; i < 64; i++) { sQt[i] = Q[i]; g_Qt[i] = Q[i]; }
        } else {
            for (int i = 0; i < 64; i++) g_Qy[i] = Q[i];
        }
    }
    __syncthreads();
    if (tid == 0) {
        for (int i = 0; i < 8; i++) {
            for (int j = 0; j < 8; j++) {
                float s = 0.0f;
                for (int k = 0; k < 8; k++) s += sQt[i * 8 + k] * sQr[k * 8 + j];
                g_G[i * 8 + j] = s;
            }
        }
        float r2[A_NUM], s2[A_NUM], sr = 0.0f, ss = 0.0f;
        for (int a = 0; a < A_NUM; a++) {
            r2[a] = kr[a] * kr[a]; sr += r2[a];
            s2[a] = ks[a] * ks[a]; ss += s2[a];
        }
        float ir = 1.0f / (sr + EPSV);
        float is = 1.0f / (ss + EPSV);
        for (int a = 0; a < A_NUM; a++) {
            g_wr[a] = r2[a] * ir;
            g_ws[a] = s2[a] * is;
        }
        float t2 = kt[0] * kt[0];
        g_t = t2 / (t2 + kphi[0] * kphi[0] + EPSV);
    }
}

// ---------------- main streaming kernel ----------------
// 128 threads/block = 16 batch elements; thread j of each 8-thread group
// owns row j of every 8x8 matrix.
// m-state rows are spilled to a self-owned smem slot (no cross-thread
// sharing -> no syncs). Row stride 12 floats: lanes hit all-distinct bank
// quads -> conflict-free.
// Congruence C = Q*A*Q^T:
//   stage 1: B_row_j = A_row_j * Q^T   (Q rows broadcast via LDS.128)
//   stage 2: row j -> sB (STS.128), syncwarp, gather with reg-cached Q row.

#define M_ROW_STRIDE 12          // floats per spilled row
#define M_A_STRIDE   96          // floats per state slice (8 rows)
#define M_EL_STRIDE  480         // floats per element (5 slices)

__device__ __forceinline__ void congruence8(const float* a,
                                            const float4* Qp,   // packed Q rows (broadcast)
                                            const float* qrow,  // reg-cached Q[j][*]
                                            int j,
                                            float* bufbase,     // smem group tile (72 floats)
                                            float* c) {
    float bb[8];
#pragma unroll
    for (int k = 0; k < 8; k++) {
        float4 q0 = Qp[2 * k];
        float4 q1 = Qp[2 * k + 1];
        float s = a[0] * q0.x;
        s = fmaf(a[1], q0.y, s);
        s = fmaf(a[2], q0.z, s);
        s = fmaf(a[3], q0.w, s);
        s = fmaf(a[4], q1.x, s);
        s = fmaf(a[5], q1.y, s);
        s = fmaf(a[6], q1.z, s);
        s = fmaf(a[7], q1.w, s);
        bb[k] = s;
    }
    __syncwarp();
    float4* bw = reinterpret_cast<float4*>(bufbase + j * 8);
    bw[0] = make_float4(bb[0], bb[1], bb[2], bb[3]);
    bw[1] = make_float4(bb[4], bb[5], bb[6], bb[7]);
    __syncwarp();
#pragma unroll
    for (int k = 0; k < 8; k++) c[k] = 0.0f;
#pragma unroll
    for (int i = 0; i < 8; i++) {
        float qji = qrow[i];
        const float4* br = reinterpret_cast<const float4*>(bufbase + i * 8);
        float4 b0 = br[0];
        float4 b1 = br[1];
        c[0] = fmaf(qji, b0.x, c[0]);
        c[1] = fmaf(qji, b0.y, c[1]);
        c[2] = fmaf(qji, b0.z, c[2]);
        c[3] = fmaf(qji, b0.w, c[3]);
        c[4] = fmaf(qji, b1.x, c[4]);
        c[5] = fmaf(qji, b1.y, c[5]);
        c[6] = fmaf(qji, b1.z, c[6]);
        c[7] = fmaf(qji, b1.w, c[7]);
    }
}

__global__ void __launch_bounds__(128, 6)
spdsru_main(const float* __restrict__ x,
            const float* __restrict__ states,
            float* __restrict__ out,
            float* __restrict__ outst) {
    __shared__ float4 sQt[16], sG[16], sQy[16];   // packed Q rows
    __shared__ float sM[16 * M_EL_STRIDE];        // per-element spilled states (30KB)
    __shared__ float sB[16 * 72];                 // congruence scratch
    __shared__ float swr[A_NUM], sws[A_NUM];
    __shared__ float sgate;

    const int tid = threadIdx.x;
    if (tid < 64) {
        reinterpret_cast<float*>(sQt)[tid] = g_Qt[tid];
        reinterpret_cast<float*>(sG)[tid]  = g_G[tid];
        reinterpret_cast<float*>(sQy)[tid] = g_Qy[tid];
    } else if (tid < 64 + A_NUM) {
        swr[tid - 64] = g_wr[tid - 64];
        sws[tid - 64] = g_ws[tid - 64];
    } else if (tid == 70) {
        sgate = g_t;
    }
    __syncthreads();

    const int grp = tid >> 3;            // 0..15
    const int j = tid & 7;
    const size_t b = (size_t)blockIdx.x * 16 + grp;
    float* bufbase = sB + grp * 72;
    float* mbase = sM + grp * M_EL_STRIDE + j * M_ROW_STRIDE;  // my row slots

    // ---- cache Q rows for stage 2 (one-time vector loads) ----
    float qtr[8], gr[8];
    {
        float4 a0 = sQt[2 * j], a1 = sQt[2 * j + 1];
        qtr[0] = a0.x; qtr[1] = a0.y; qtr[2] = a0.z; qtr[3] = a0.w;
        qtr[4] = a1.x; qtr[5] = a1.y; qtr[6] = a1.z; qtr[7] = a1.w;
        float4 g0 = sG[2 * j], g1 = sG[2 * j + 1];
        gr[0] = g0.x; gr[1] = g0.y; gr[2] = g0.z; gr[3] = g0.w;
        gr[4] = g1.x; gr[5] = g1.y; gr[6] = g1.z; gr[7] = g1.w;
    }

    // ---- load x row ----
    const float4* xp = reinterpret_cast<const float4*>(x + b * 64 + j * 8);
    float4 xa = xp[0], xb = xp[1];
    float xr[8] = {xa.x, xa.y, xa.z, xa.w, xb.x, xb.y, xb.z, xb.w};

    // ---- load state rows: accumulate Yt in-flight, spill rows to smem ----
    float yt[8];
#pragma unroll
    for (int k = 0; k < 8; k++) yt[k] = 0.0f;
#pragma unroll
    for (int a = 0; a < A_NUM; a++) {
        const float4* mp = reinterpret_cast<const float4*>(states + b * 320 + a * 64 + j * 8);
        float4 m0 = mp[0], m1 = mp[1];
        float wa = swr[a];
        yt[0] = fmaf(wa, m0.x, yt[0]);
        yt[1] = fmaf(wa, m0.y, yt[1]);
        yt[2] = fmaf(wa, m0.z, yt[2]);
        yt[3] = fmaf(wa, m0.w, yt[3]);
        yt[4] = fmaf(wa, m1.x, yt[4]);
        yt[5] = fmaf(wa, m1.y, yt[5]);
        yt[6] = fmaf(wa, m1.z, yt[6]);
        yt[7] = fmaf(wa, m1.w, yt[7]);
        float4* sp = reinterpret_cast<float4*>(mbase + a * M_A_STRIDE);
        sp[0] = m0;
        sp[1] = m1;
    }

    // ---- U = Qt*Xt*Qt^T ;  V = G*Yt*G^T  (G = Qt*Qr) ----
    float u[8], v[8];
    congruence8(xr, sQt, qtr, j, bufbase, u);
    congruence8(yt, sG, gr, j, bufbase, v);

    // ---- Phit = (1-t)*U + t*V ----
    const float t = sgate;
    float phit[8];
#pragma unroll
    for (int k = 0; k < 8; k++) phit[k] = fmaf(t, v[k] - u[k], u[k]);

    // ---- Mt[a] = (1-alpha)*M[a] + alpha*Phit ; St = sum ws[a]*Mt[a] ----
    const float alpha[A_NUM] = {0.01f, 0.25f, 0.5f, 0.9f, 0.99f};
    float st[8];
#pragma unroll
    for (int k = 0; k < 8; k++) st[k] = 0.0f;
#pragma unroll
    for (int a = 0; a < A_NUM; a++) {
        const float4* sp = reinterpret_cast<const float4*>(mbase + a * M_A_STRIDE);
        float4 m0 = sp[0], m1 = sp[1];
        float mm[8] = {m0.x, m0.y, m0.z, m0.w, m1.x, m1.y, m1.z, m1.w};
        float mt[8];
        float wsa = sws[a];
#pragma unroll
        for (int k = 0; k < 8; k++) {
            mt[k] = fmaf(alpha[a], phit[k] - mm[k], mm[k]);
            st[k] = fmaf(wsa, mt[k], st[k]);
        }
        float4* op = reinterpret_cast<float4*>(outst + b * 320 + a * 64 + j * 8);
        op[0] = make_float4(mt[0], mt[1], mt[2], mt[3]);
        op[1] = make_float4(mt[4], mt[5], mt[6], mt[7]);
    }

    // ---- Ot = Qy * St * Qy^T ---- (load Qy row late to shorten liveness)
    float qyr[8];
    {
        float4 y0 = sQy[2 * j], y1 = sQy[2 * j + 1];
        qyr[0] = y0.x; qyr[1] = y0.y; qyr[2] = y0.z; qyr[3] = y0.w;
        qyr[4] = y1.x; qyr[5] = y1.y; qyr[6] = y1.z; qyr[7] = y1.w;
    }
    float ot[8];
    congruence8(st, sQy, qyr, j, bufbase, ot);
    float4* oo = reinterpret_cast<float4*>(out + b * 64 + j * 8);
    oo[0] = make_float4(ot[0], ot[1], ot[2], ot[3]);
    oo[1] = make_float4(ot[4], ot[5], ot[6], ot[7]);
}

extern "C" void kernel_launch(void* const* d_in, const int* in_sizes, int n_in,
                              void* d_out, int out_size) {
    const float* x      = (const float*)d_in[0];
    const float* states = (const float*)d_in[1];
    const float* kr     = (const float*)d_in[2];
    const float* kt     = (const float*)d_in[3];
    const float* kphi   = (const float*)d_in[4];
    const float* ks     = (const float*)d_in[5];
    const float* br     = (const float*)d_in[6];
    const float* bt     = (const float*)d_in[7];
    const float* by     = (const float*)d_in[8];

    const int batch = in_sizes[0] / 64;

    float* out   = (float*)d_out;
    float* outst = out + (size_t)batch * 64;

    spdsru_prologue<<<1, 32>>>(kr, kt, kphi, ks, br, bt, by);

    int blocks = batch / 16;
    spdsru_main<<<blocks, 128>>>(x, states, out, outst);
}